// round 14
// baseline (speedup 1.0000x reference)
#include <cuda_runtime.h>

#define IC 1152
#define OC 10
#define ID 8
#define OD 16
#define OD2 8          // packed f32x2 pairs (full od per thread)
#define BATCH 32
#define NITER 5
#define EPSV 1e-20f
#define ICPB 8         // per block, as 4 pairs; thread parity picks ic within pair
#define NPAIR 4
#define NTHREADS 640   // 20 warps: warp = oc*2+par, lane = b
#define WSLAB (OC * ID * OD)   // 1280 floats per ic

typedef unsigned long long u64;

__device__ __forceinline__ u64 pk2(float lo, float hi) {
    u64 r; asm("mov.b64 %0, {%1,%2};" : "=l"(r) : "f"(lo), "f"(hi)); return r;
}
__device__ __forceinline__ float2 upk2(u64 v) {
    float2 f; asm("mov.b64 {%0,%1}, %2;" : "=f"(f.x), "=f"(f.y) : "l"(v)); return f;
}
__device__ __forceinline__ u64 mul2(u64 a, u64 b) {
    u64 r; asm("mul.rn.f32x2 %0, %1, %2;" : "=l"(r) : "l"(a), "l"(b)); return r;
}
__device__ __forceinline__ u64 add2(u64 a, u64 b) {
    u64 r; asm("add.rn.f32x2 %0, %1, %2;" : "=l"(r) : "l"(a), "l"(b)); return r;
}
__device__ __forceinline__ u64 fma2(u64 a, u64 b, u64 c) {
    u64 r; asm("fma.rn.f32x2 %0, %1, %2, %3;" : "=l"(r) : "l"(a), "l"(b), "l"(c)); return r;
}
__device__ __forceinline__ unsigned smem_u32(const void* p) {
    return (unsigned)__cvta_generic_to_shared(p);
}
__device__ __forceinline__ void cp_async16(unsigned dst, const void* src) {
    asm volatile("cp.async.ca.shared.global [%0], [%1], 16;" :: "r"(dst), "l"(src));
}

__global__ void zero_out_kernel(float* out, int n) {
    int i = blockIdx.x * blockDim.x + threadIdx.x;
    if (i < n) out[i] = 0.0f;
}

__global__ __launch_bounds__(NTHREADS, 1)
void caps_kernel(const float* __restrict__ x,
                 const float* __restrict__ w,
                 float* __restrict__ out) {
    __shared__ __align__(16) float w_s[2][2 * WSLAB];   // [buf][par-slab] pair, dbl-buffered
    __shared__ float x_s[ICPB][BATCH][ID + 1];          // pre-normalized x, stride 9
    __shared__ float alpha_s[2][BATCH][OC + 1];         // [par][b][oc], padded (11)

    const int tid  = threadIdx.x;
    const int b    = tid & 31;                 // lane
    const int warp = tid >> 5;                 // 0..19
    const int oc   = warp >> 1;
    const int par  = warp & 1;                 // ic parity within pair
    const int ic0  = blockIdx.x * ICPB;

    // ---- cp.async pair 0 (2 slabs = 640 float4, one per thread) ----
    cp_async16(smem_u32((float4*)&w_s[0][0] + tid),
               (const float4*)(w + (size_t)ic0 * WSLAB) + tid);
    asm volatile("cp.async.commit_group;");

    // ---- load + normalize ALL x for this block's 8 ics (once) ----
    if (tid < ICPB * BATCH) {
        const int kk = tid >> 5, bb = tid & 31;
        const float* xp = x + ((size_t)bb * IC + ic0 + kk) * ID;
        float v[ID]; float sum = 0.0f;
#pragma unroll
        for (int id = 0; id < ID; id++) { v[id] = xp[id]; sum += v[id]; }
        float r = __fdividef(1.0f, sum + EPSV);
#pragma unroll
        for (int id = 0; id < ID; id++) x_s[kk][bb][id] = v[id] * r;
    }
    asm volatile("cp.async.wait_group 0;");
    __syncthreads();

    u64 res2[OD2];
#pragma unroll
    for (int j = 0; j < OD2; j++) res2[j] = 0ull;

    for (int p = 0; p < NPAIR; p++) {
        const int buf = p & 1;

        // ---- prefetch next pair (async, zero registers) ----
        if (p + 1 < NPAIR) {
            cp_async16(smem_u32((float4*)&w_s[buf ^ 1][0] + tid),
                       (const float4*)(w + (size_t)(ic0 + 2 * (p + 1)) * WSLAB) + tid);
            asm volatile("cp.async.commit_group;");
        }

        const int kk = 2 * p + par;                     // this thread's ic index
        const float* xk = &x_s[kk][b][0];               // normalized x (bcast reads)
        const ulonglong2* wv = reinterpret_cast<const ulonglong2*>(
            &w_s[buf][par * WSLAB] + oc * ID * OD);     // full rows, 4 vec each

        // ---- NNMF, fused rows: each weight row loaded once per iteration ----
        u64 outv2[OD2];
#pragma unroll
        for (int j = 0; j < OD2; j++) outv2[j] = pk2(1.0f / OD, 1.0f / OD);

#pragma unroll
        for (int it = 0; it < NITER; it++) {
            u64 t[OD2];
#pragma unroll
            for (int j = 0; j < OD2; j++) t[j] = 0ull;
#pragma unroll
            for (int id = 0; id < ID; id++) {
                ulonglong2 q0 = wv[id * 4 + 0];
                ulonglong2 q1 = wv[id * 4 + 1];
                ulonglong2 q2 = wv[id * 4 + 2];
                ulonglong2 q3 = wv[id * 4 + 3];
                u64 a0 = mul2(outv2[0], q0.x);
                u64 a1 = mul2(outv2[1], q0.y);
                a0 = fma2(outv2[2], q1.x, a0);
                a1 = fma2(outv2[3], q1.y, a1);
                a0 = fma2(outv2[4], q2.x, a0);
                a1 = fma2(outv2[5], q2.y, a1);
                a0 = fma2(outv2[6], q3.x, a0);
                a1 = fma2(outv2[7], q3.y, a1);
                float2 f = upk2(add2(a0, a1));
                float s = __fdividef(xk[id], f.x + f.y + EPSV);
                u64 sp = pk2(s, s);
                t[0] = fma2(sp, q0.x, t[0]);
                t[1] = fma2(sp, q0.y, t[1]);
                t[2] = fma2(sp, q1.x, t[2]);
                t[3] = fma2(sp, q1.y, t[3]);
                t[4] = fma2(sp, q2.x, t[4]);
                t[5] = fma2(sp, q2.y, t[5]);
                t[6] = fma2(sp, q3.x, t[6]);
                t[7] = fma2(sp, q3.y, t[7]);
            }
#pragma unroll
            for (int j = 0; j < OD2; j++)
                outv2[j] = mul2(outv2[j], t[j]);
        }

        // ---- final normalization over OD ----
        {
            u64 t01 = add2(outv2[0], outv2[1]), t23 = add2(outv2[2], outv2[3]);
            u64 t45 = add2(outv2[4], outv2[5]), t67 = add2(outv2[6], outv2[7]);
            float2 tf = upk2(add2(add2(t01, t23), add2(t45, t67)));
            float rn = __fdividef(1.0f, tf.x + tf.y + EPSV);
            u64 rn2 = pk2(rn, rn);
#pragma unroll
            for (int j = 0; j < OD2; j++) outv2[j] = mul2(outv2[j], rn2);
        }

        // ---- reconstruct + alpha (fused row pass, no cross-thread ops) ----
        float alpha = 0.0f;
#pragma unroll
        for (int id = 0; id < ID; id++) {
            ulonglong2 q0 = wv[id * 4 + 0];
            ulonglong2 q1 = wv[id * 4 + 1];
            ulonglong2 q2 = wv[id * 4 + 2];
            ulonglong2 q3 = wv[id * 4 + 3];
            u64 a0 = mul2(outv2[0], q0.x);
            u64 a1 = mul2(outv2[1], q0.y);
            a0 = fma2(outv2[2], q1.x, a0);
            a1 = fma2(outv2[3], q1.y, a1);
            a0 = fma2(outv2[4], q2.x, a0);
            a1 = fma2(outv2[5], q2.y, a1);
            a0 = fma2(outv2[6], q3.x, a0);
            a1 = fma2(outv2[7], q3.y, a1);
            float2 rf = upk2(add2(a0, a1));
            alpha = fmaf(rf.x + rf.y, xk[id], alpha);
        }

        alpha_s[par][b][oc] = alpha;
        __syncthreads();   // alpha visible for this pair

        float asum = 0.0f;
#pragma unroll
        for (int o2 = 0; o2 < OC; o2++) asum += alpha_s[par][b][o2];
        float an = alpha * __fdividef(1.0f, asum + EPSV);
        u64 an2 = pk2(an, an);
#pragma unroll
        for (int j = 0; j < OD2; j++)
            res2[j] = fma2(outv2[j], an2, res2[j]);

        // ---- next pair ready + alpha_s safe to rewrite ----
        if (p + 1 < NPAIR)
            asm volatile("cp.async.wait_group 0;");
        __syncthreads();
    }

    // ---- single flush: 288 adds per address (144 blocks × 2 parities) ----
    float* ob = &out[(b * OC + oc) * OD];
#pragma unroll
    for (int j = 0; j < OD2; j++) {
        float2 f = upk2(res2[j]);
        atomicAdd(ob + 2 * j,     f.x);
        atomicAdd(ob + 2 * j + 1, f.y);
    }
}

extern "C" void kernel_launch(void* const* d_in, const int* in_sizes, int n_in,
                              void* d_out, int out_size) {
    const float* x = (const float*)d_in[0];   // [32, 1152, 8]
    const float* w = (const float*)d_in[1];   // [1152, 10, 8, 16]
    float* out = (float*)d_out;               // [32, 10, 16]

    zero_out_kernel<<<(BATCH * OC * OD + 255) / 256, 256>>>(out, BATCH * OC * OD);
    caps_kernel<<<IC / ICPB, NTHREADS>>>(x, w, out);   // grid = 144 = one wave
}

// round 15
// speedup vs baseline: 2.2698x; 2.2698x over previous
#include <cuda_runtime.h>

#define IC 1152
#define OC 10
#define ID 8
#define OD 16
#define OD4 4          // packed f32x2 pairs per od-half
#define BATCH 32
#define NITER 5
#define EPSV 1e-20f
#define ICPB 8
#define NTHREADS 640   // 20 warps: warp=(oc,b-half), lane=odh*16+b%16
#define WSLAB (OC * ID * OD)   // 1280 floats per ic

typedef unsigned long long u64;

__device__ __forceinline__ u64 pk2(float lo, float hi) {
    u64 r; asm("mov.b64 %0, {%1,%2};" : "=l"(r) : "f"(lo), "f"(hi)); return r;
}
__device__ __forceinline__ float2 upk2(u64 v) {
    float2 f; asm("mov.b64 {%0,%1}, %2;" : "=f"(f.x), "=f"(f.y) : "l"(v)); return f;
}
__device__ __forceinline__ u64 mul2(u64 a, u64 b) {
    u64 r; asm("mul.rn.f32x2 %0, %1, %2;" : "=l"(r) : "l"(a), "l"(b)); return r;
}
__device__ __forceinline__ u64 add2(u64 a, u64 b) {
    u64 r; asm("add.rn.f32x2 %0, %1, %2;" : "=l"(r) : "l"(a), "l"(b)); return r;
}
__device__ __forceinline__ u64 fma2(u64 a, u64 b, u64 c) {
    u64 r; asm("fma.rn.f32x2 %0, %1, %2, %3;" : "=l"(r) : "l"(a), "l"(b), "l"(c)); return r;
}

__global__ void zero_out_kernel(float* out, int n) {
    int i = blockIdx.x * blockDim.x + threadIdx.x;
    if (i < n) out[i] = 0.0f;
}

__global__ __launch_bounds__(NTHREADS, 1)
void caps_kernel(const float* __restrict__ x,
                 const float* __restrict__ w,
                 float* __restrict__ out) {
    __shared__ __align__(16) float w_s[WSLAB];
    __shared__ float x_s[BATCH][ID + 1];            // stride 9: conflict-free
    __shared__ float alpha_s[BATCH][OC];

    const int tid  = threadIdx.x;
    const int lane = tid & 31;
    const int warp = tid >> 5;                      // 0..19
    const int oc   = warp >> 1;                     // warp pair -> oc
    const int b    = ((warp & 1) << 4) | (lane & 15);
    const int odh  = lane >> 4;                     // od half: 0 or 1

    u64 res2[OD4];
#pragma unroll
    for (int j = 0; j < OD4; j++) res2[j] = 0ull;

    // ---- load slab 0 + x for ic0 ----
    {
        const int ic0 = blockIdx.x * ICPB;
        w_s[tid]            = w[ic0 * WSLAB + tid];
        w_s[tid + NTHREADS] = w[ic0 * WSLAB + tid + NTHREADS];
        if (tid < BATCH * ID) {
            int bb = tid >> 3, id = tid & 7;
            x_s[bb][id] = x[(bb * IC + ic0) * ID + id];
        }
    }
    __syncthreads();

    for (int k = 0; k < ICPB; k++) {
        const int ic = blockIdx.x * ICPB + k;

        // ---- register-prefetch next slab (3 regs) ----
        float wpre0 = 0.f, wpre1 = 0.f, xpre = 0.f;
        if (k + 1 < ICPB) {
            const float* wn = w + (size_t)(ic + 1) * WSLAB;
            wpre0 = wn[tid];
            wpre1 = wn[tid + NTHREADS];
            if (tid < BATCH * ID)
                xpre = x[((tid >> 3) * IC + ic + 1) * ID + (tid & 7)];
        }

        // ---- normalize x over ID ----
        float xn[ID];
        float xs = 0.0f;
#pragma unroll
        for (int id = 0; id < ID; id++) { xn[id] = x_s[b][id]; xs += xn[id]; }
        float xr = __fdividef(1.0f, xs + EPSV);
#pragma unroll
        for (int id = 0; id < ID; id++) xn[id] *= xr;

        // this thread's od-half of each weight row: 2 ulonglong2 per id
        const ulonglong2* wv =
            reinterpret_cast<const ulonglong2*>(w_s + oc * ID * OD) + odh * 2;

        // ---- NNMF factored + FUSED row pass:
        //   per id: load half-row once -> half-dot -> shfl(16) combine
        //           -> rcp -> accumulate t from SAME registers
        u64 outv2[OD4];
#pragma unroll
        for (int j = 0; j < OD4; j++) outv2[j] = pk2(1.0f / OD, 1.0f / OD);

#pragma unroll
        for (int it = 0; it < NITER; it++) {
            u64 t[OD4];
#pragma unroll
            for (int j = 0; j < OD4; j++) t[j] = 0ull;

#pragma unroll
            for (int id = 0; id < ID; id++) {
                ulonglong2 q0 = wv[id * 4];
                ulonglong2 q1 = wv[id * 4 + 1];
                u64 a0 = mul2(outv2[0], q0.x);
                u64 a1 = mul2(outv2[1], q0.y);
                a0 = fma2(outv2[2], q1.x, a0);
                a1 = fma2(outv2[3], q1.y, a1);
                float2 f = upk2(add2(a0, a1));
                float loc = f.x + f.y;
                float tot = loc + __shfl_xor_sync(0xFFFFFFFFu, loc, 16);
                float s = __fdividef(xn[id], tot + EPSV);
                u64 sp = pk2(s, s);
                t[0] = fma2(sp, q0.x, t[0]);
                t[1] = fma2(sp, q0.y, t[1]);
                t[2] = fma2(sp, q1.x, t[2]);
                t[3] = fma2(sp, q1.y, t[3]);
            }
#pragma unroll
            for (int j = 0; j < OD4; j++)
                outv2[j] = mul2(outv2[j], t[j]);
        }

        // ---- final normalization over OD (cross-partner) ----
        {
            float2 tf = upk2(add2(add2(outv2[0], outv2[1]),
                                  add2(outv2[2], outv2[3])));
            float loc = tf.x + tf.y;
            float tot = loc + __shfl_xor_sync(0xFFFFFFFFu, loc, 16);
            float rn = __fdividef(1.0f, tot + EPSV);
            u64 rn2 = pk2(rn, rn);
#pragma unroll
            for (int j = 0; j < OD4; j++) outv2[j] = mul2(outv2[j], rn2);
        }

        // ---- reconstruct + alpha (half-dots, one combine at the end) ----
        float ap = 0.0f;
#pragma unroll
        for (int id = 0; id < ID; id++) {
            ulonglong2 q0 = wv[id * 4];
            ulonglong2 q1 = wv[id * 4 + 1];
            u64 a0 = mul2(outv2[0], q0.x);
            u64 a1 = mul2(outv2[1], q0.y);
            a0 = fma2(outv2[2], q1.x, a0);
            a1 = fma2(outv2[3], q1.y, a1);
            float2 rf = upk2(add2(a0, a1));
            ap = fmaf(rf.x + rf.y, xn[id], ap);
        }
        float alpha = ap + __shfl_xor_sync(0xFFFFFFFFu, ap, 16);

        if (odh == 0) alpha_s[b][oc] = alpha;
        __syncthreads();   // alpha visible; all w_s/x_s reads complete

        // ---- store prefetched slab ----
        if (k + 1 < ICPB) {
            w_s[tid]            = wpre0;
            w_s[tid + NTHREADS] = wpre1;
            if (tid < BATCH * ID)
                x_s[tid >> 3][tid & 7] = xpre;
        }

        float asum = 0.0f;
#pragma unroll
        for (int o2 = 0; o2 < OC; o2++) asum += alpha_s[b][o2];
        float an = alpha * __fdividef(1.0f, asum + EPSV);
        u64 an2 = pk2(an, an);
#pragma unroll
        for (int j = 0; j < OD4; j++)
            res2[j] = fma2(outv2[j], an2, res2[j]);

        __syncthreads();   // new slab visible + alpha_s reads complete
    }

    // ---- accumulate over ic (144 adds per address — cheap) ----
    float* ob = &out[(b * OC + oc) * OD + odh * 8];
#pragma unroll
    for (int j = 0; j < OD4; j++) {
        float2 f = upk2(res2[j]);
        atomicAdd(ob + 2 * j,     f.x);
        atomicAdd(ob + 2 * j + 1, f.y);
    }
}

extern "C" void kernel_launch(void* const* d_in, const int* in_sizes, int n_in,
                              void* d_out, int out_size) {
    const float* x = (const float*)d_in[0];   // [32, 1152, 8]
    const float* w = (const float*)d_in[1];   // [1152, 10, 8, 16]
    float* out = (float*)d_out;               // [32, 10, 16]

    zero_out_kernel<<<(BATCH * OC * OD + 255) / 256, 256>>>(out, BATCH * OC * OD);
    caps_kernel<<<IC / ICPB, NTHREADS>>>(x, w, out);   // grid = 144 = one wave
}

// round 16
// speedup vs baseline: 2.6158x; 1.1525x over previous
#include <cuda_runtime.h>

#define IC 1152
#define OC 10
#define ID 8
#define OD 16
#define OD4 4          // packed f32x2 pairs per od-half
#define BATCH 32
#define NITER 5
#define EPSV 1e-20f
#define ICPB 8
#define NTHREADS 640   // 20 warps: warp=(oc,b-half), lane=odh*16+b%16
#define WSLAB (OC * ID * OD)   // 1280 floats per ic

typedef unsigned long long u64;

__device__ __forceinline__ u64 pk2(float lo, float hi) {
    u64 r; asm("mov.b64 %0, {%1,%2};" : "=l"(r) : "f"(lo), "f"(hi)); return r;
}
__device__ __forceinline__ float2 upk2(u64 v) {
    float2 f; asm("mov.b64 {%0,%1}, %2;" : "=f"(f.x), "=f"(f.y) : "l"(v)); return f;
}
__device__ __forceinline__ u64 mul2(u64 a, u64 b) {
    u64 r; asm("mul.rn.f32x2 %0, %1, %2;" : "=l"(r) : "l"(a), "l"(b)); return r;
}
__device__ __forceinline__ u64 add2(u64 a, u64 b) {
    u64 r; asm("add.rn.f32x2 %0, %1, %2;" : "=l"(r) : "l"(a), "l"(b)); return r;
}
__device__ __forceinline__ u64 fma2(u64 a, u64 b, u64 c) {
    u64 r; asm("fma.rn.f32x2 %0, %1, %2, %3;" : "=l"(r) : "l"(a), "l"(b), "l"(c)); return r;
}
__device__ __forceinline__ unsigned smem_u32(const void* p) {
    return (unsigned)__cvta_generic_to_shared(p);
}
__device__ __forceinline__ void cp_async16(unsigned dst, const void* src) {
    asm volatile("cp.async.ca.shared.global [%0], [%1], 16;" :: "r"(dst), "l"(src));
}

__global__ void zero_out_kernel(float* out, int n) {
    int i = blockIdx.x * blockDim.x + threadIdx.x;
    if (i < n) out[i] = 0.0f;
}

__global__ __launch_bounds__(NTHREADS, 1)
void caps_kernel(const float* __restrict__ x,
                 const float* __restrict__ w,
                 float* __restrict__ out) {
    __shared__ __align__(16) float w_s[2][WSLAB];   // double-buffered ic slab
    __shared__ float x_s[ICPB][BATCH][ID + 1];      // RAW x (norm cancels), stride 9
    __shared__ float alpha_s[2][BATCH][OC];         // parity double-buffered

    const int tid  = threadIdx.x;
    const int lane = tid & 31;
    const int warp = tid >> 5;                      // 0..19
    const int oc   = warp >> 1;
    const int b    = ((warp & 1) << 4) | (lane & 15);
    const int odh  = lane >> 4;                     // od half: 0 or 1
    const int ic0  = blockIdx.x * ICPB;

    // ---- cp.async slab 0 ----
    if (tid < WSLAB / 4)
        cp_async16(smem_u32((float4*)&w_s[0][0] + tid),
                   (const float4*)(w + (size_t)ic0 * WSLAB) + tid);
    asm volatile("cp.async.commit_group;");

    // ---- load ALL x for this block's 8 ics, raw (normalization cancels) ----
    for (int i = tid; i < ICPB * BATCH * ID; i += NTHREADS) {
        int kk = i >> 8, rem = i & 255, bb = rem >> 3, id = rem & 7;
        x_s[kk][bb][id] = x[((size_t)bb * IC + ic0 + kk) * ID + id];
    }
    asm volatile("cp.async.wait_group 0;");
    __syncthreads();

    u64 res2[OD4];
#pragma unroll
    for (int j = 0; j < OD4; j++) res2[j] = 0ull;

    for (int k = 0; k < ICPB; k++) {
        const int buf = k & 1;

        // ---- prefetch next slab into other buffer (async, zero regs) ----
        if (k + 1 < ICPB && tid < WSLAB / 4)
            cp_async16(smem_u32((float4*)&w_s[buf ^ 1][0] + tid),
                       (const float4*)(w + (size_t)(ic0 + k + 1) * WSLAB) + tid);
        asm volatile("cp.async.commit_group;");

        float xv[ID];
#pragma unroll
        for (int id = 0; id < ID; id++) xv[id] = x_s[k][b][id];

        const ulonglong2* wv =
            reinterpret_cast<const ulonglong2*>(&w_s[buf][0] + oc * ID * OD) + odh * 2;

        // ---- NNMF, fused rows, all normalizations deferred (scale-invariant) ----
        u64 outv2[OD4];
#pragma unroll
        for (int j = 0; j < OD4; j++) outv2[j] = pk2(1.0f, 1.0f);

#pragma unroll
        for (int it = 0; it < NITER; it++) {
            u64 t[OD4];
#pragma unroll
            for (int j = 0; j < OD4; j++) t[j] = 0ull;
#pragma unroll
            for (int id = 0; id < ID; id++) {
                ulonglong2 q0 = wv[id * 4];
                ulonglong2 q1 = wv[id * 4 + 1];
                u64 a = mul2(outv2[0], q0.x);
                a = fma2(outv2[1], q0.y, a);
                a = fma2(outv2[2], q1.x, a);
                a = fma2(outv2[3], q1.y, a);
                float2 f = upk2(a);
                float loc = f.x + f.y;
                float tot = loc + __shfl_xor_sync(0xFFFFFFFFu, loc, 16);
                float s = __fdividef(xv[id], tot + EPSV);
                u64 sp = pk2(s, s);
                t[0] = fma2(sp, q0.x, t[0]);
                t[1] = fma2(sp, q0.y, t[1]);
                t[2] = fma2(sp, q1.x, t[2]);
                t[3] = fma2(sp, q1.y, t[3]);
            }
#pragma unroll
            for (int j = 0; j < OD4; j++)
                outv2[j] = mul2(outv2[j], t[j]);
        }

        // ---- S = Σ_od outv (raw); rn = 1/S folded into output scale ----
        float rn;
        {
            float2 sf = upk2(add2(add2(outv2[0], outv2[1]),
                                  add2(outv2[2], outv2[3])));
            float Sl = sf.x + sf.y;
            float St = Sl + __shfl_xor_sync(0xFFFFFFFFu, Sl, 16);
            rn = __fdividef(1.0f, St + EPSV);
        }

        // ---- alpha via v-trick: v[j] = Σ_id x[id]·w[id][j]; A = outv·v ----
        float alpha;
        {
            u64 v0 = 0ull, v1 = 0ull, v2 = 0ull, v3 = 0ull;
#pragma unroll
            for (int id = 0; id < ID; id++) {
                u64 xp = pk2(xv[id], xv[id]);
                ulonglong2 q0 = wv[id * 4];
                ulonglong2 q1 = wv[id * 4 + 1];
                v0 = fma2(xp, q0.x, v0);
                v1 = fma2(xp, q0.y, v1);
                v2 = fma2(xp, q1.x, v2);
                v3 = fma2(xp, q1.y, v3);
            }
            u64 a = mul2(outv2[0], v0);
            a = fma2(outv2[1], v1, a);
            a = fma2(outv2[2], v2, a);
            a = fma2(outv2[3], v3, a);
            float2 af = upk2(a);
            float Al = af.x + af.y;
            float At = Al + __shfl_xor_sync(0xFFFFFFFFu, Al, 16);
            alpha = At * rn;
        }

        if (odh == 0) alpha_s[buf][b][oc] = alpha;

        // ---- the ONE barrier per ic: alpha visible + next slab landed;
        //      w_s reads of this buf are done above, cp.async into buf^1 safe ----
        if (k + 1 < ICPB)
            asm volatile("cp.async.wait_group 0;");
        __syncthreads();

        float asum = 0.0f;
#pragma unroll
        for (int o2 = 0; o2 < OC; o2++) asum += alpha_s[buf][b][o2];
        float scale = alpha * __fdividef(rn, asum + EPSV);   // (α/Σα)·(1/S)
        u64 sc2 = pk2(scale, scale);
#pragma unroll
        for (int j = 0; j < OD4; j++)
            res2[j] = fma2(outv2[j], sc2, res2[j]);
    }

    // ---- accumulate over ic (144 adds per address — cheap) ----
    float* ob = &out[(b * OC + oc) * OD + odh * 8];
#pragma unroll
    for (int j = 0; j < OD4; j++) {
        float2 f = upk2(res2[j]);
        atomicAdd(ob + 2 * j,     f.x);
        atomicAdd(ob + 2 * j + 1, f.y);
    }
}

extern "C" void kernel_launch(void* const* d_in, const int* in_sizes, int n_in,
                              void* d_out, int out_size) {
    const float* x = (const float*)d_in[0];   // [32, 1152, 8]
    const float* w = (const float*)d_in[1];   // [1152, 10, 8, 16]
    float* out = (float*)d_out;               // [32, 10, 16]

    zero_out_kernel<<<(BATCH * OC * OD + 255) / 256, 256>>>(out, BATCH * OC * OD);
    caps_kernel<<<IC / ICPB, NTHREADS>>>(x, w, out);   // grid = 144 = one wave
}